// round 1
// baseline (speedup 1.0000x reference)
#include <cuda_runtime.h>
#include <cstdint>

#define N_NODES 40000
#define N_EDGES 640000
#define D_FEAT  128

// Scratch (allocation-free: __device__ globals)
__device__ float              g_ee[N_EDGES];    // exp(e) per edge
__device__ unsigned long long g_sum[N_NODES];   // fixed-point (2^32) segment sums

// ---------------------------------------------------------------------------
// Kernel 1: zero the per-node sums
// ---------------------------------------------------------------------------
__global__ void zero_sums_kernel() {
    int i = blockIdx.x * blockDim.x + threadIdx.x;
    if (i < N_NODES) g_sum[i] = 0ULL;
}

// ---------------------------------------------------------------------------
// Kernel 2: warp per edge.
//   lane l loads float4 #l of feats[src] and feats[dst] (128 floats = 32 x float4),
//   L1 distance via warp shfl reduction, then:
//     e  = exp(-0.01 * L1)          in (0, 1]
//     ee = exp(e)                    in (1, 2.72]   (max-subtraction unnecessary)
//   lane 0 stores ee and atomically accumulates fixed-point ee into g_sum[dst].
// ---------------------------------------------------------------------------
__global__ __launch_bounds__(256) void edge_kernel(const float4* __restrict__ feats4,
                                                   const int* __restrict__ src,
                                                   const int* __restrict__ dst) {
    int edge = (blockIdx.x * blockDim.x + threadIdx.x) >> 5;
    int lane = threadIdx.x & 31;
    if (edge >= N_EDGES) return;

    int s = src[edge];          // broadcast load (same addr across warp)
    int d = dst[edge];

    float4 a = feats4[(size_t)s * (D_FEAT / 4) + lane];
    float4 b = feats4[(size_t)d * (D_FEAT / 4) + lane];

    float t = fabsf(a.x - b.x) + fabsf(a.y - b.y) +
              fabsf(a.z - b.z) + fabsf(a.w - b.w);

    t += __shfl_xor_sync(0xffffffffu, t, 16);
    t += __shfl_xor_sync(0xffffffffu, t, 8);
    t += __shfl_xor_sync(0xffffffffu, t, 4);
    t += __shfl_xor_sync(0xffffffffu, t, 2);
    t += __shfl_xor_sync(0xffffffffu, t, 1);

    if (lane == 0) {
        float e  = __expf(-0.01f * t);
        float ee = __expf(e);
        g_ee[edge] = ee;
        // fixed-point (2^32) accumulation: deterministic (integer add is associative)
        unsigned long long q = (unsigned long long)(ee * 4294967296.0f);
        atomicAdd(&g_sum[d], q);
    }
}

// ---------------------------------------------------------------------------
// Kernel 3: out[i] = ee[i] / sum[dst[i]]
// ---------------------------------------------------------------------------
__global__ __launch_bounds__(256) void finalize_kernel(const int* __restrict__ dst,
                                                       float* __restrict__ out) {
    int i = blockIdx.x * blockDim.x + threadIdx.x;
    if (i < N_EDGES) {
        float s = (float)g_sum[dst[i]] * 0x1p-32f;
        out[i] = g_ee[i] / s;
    }
}

// ---------------------------------------------------------------------------
extern "C" void kernel_launch(void* const* d_in, const int* in_sizes, int n_in,
                              void* d_out, int out_size) {
    const float4* feats4 = (const float4*)d_in[0];
    const int*    src    = (const int*)d_in[1];
    const int*    dst    = (const int*)d_in[2];
    float*        out    = (float*)d_out;

    zero_sums_kernel<<<(N_NODES + 255) / 256, 256>>>();

    // warp per edge: 640000 warps = 640000*32 threads; 256 threads/block -> 8 edges/block
    edge_kernel<<<(N_EDGES * 32) / 256, 256>>>(feats4, src, dst);

    finalize_kernel<<<(N_EDGES + 255) / 256, 256>>>(dst, out);
}

// round 2
// speedup vs baseline: 1.6188x; 1.6188x over previous
#include <cuda_runtime.h>
#include <cuda_fp16.h>
#include <cstdint>

#define N_NODES 40000
#define N_EDGES 640000
#define D_FEAT  128

// Scratch (allocation-free: __device__ globals)
__device__ __half2            g_fh[N_NODES * D_FEAT / 2];  // fp16 copy of feats (10.2 MB)
__device__ float              g_ee[N_EDGES];                // exp(e) per edge
__device__ unsigned long long g_sum[N_NODES];               // fixed-point (2^32) segment sums

// ---------------------------------------------------------------------------
// Kernel 1: convert feats fp32 -> fp16, and zero the per-node sums (fused).
// Each thread converts 4 floats (one float4 -> one uint2 of 2x half2).
// ---------------------------------------------------------------------------
__global__ __launch_bounds__(256) void convert_kernel(const float4* __restrict__ feats4) {
    int i = blockIdx.x * blockDim.x + threadIdx.x;        // [0, N_NODES*D_FEAT/4)
    if (i < N_NODES * D_FEAT / 4) {
        float4 v = feats4[i];
        g_fh[2 * i + 0] = __floats2half2_rn(v.x, v.y);
        g_fh[2 * i + 1] = __floats2half2_rn(v.z, v.w);
    }
    if (i < N_NODES) g_sum[i] = 0ULL;
}

// ---------------------------------------------------------------------------
// Kernel 2: 16 lanes per edge (2 edges per warp).
//   lane l loads uint4 #l (= 8 halves) of row src and row dst (row = 16 uint4),
//   fp16 sub/abs, fp32 accumulate, 4-step shfl reduction over the half-warp.
//     e  = exp(-0.01 * L1)   in (0, 1]
//     ee = exp(e)            in (1, 2.72]  (segment-max subtraction unnecessary)
//   lane 0 stores ee and atomically accumulates fixed-point ee into g_sum[dst].
// ---------------------------------------------------------------------------
__global__ __launch_bounds__(256) void edge_kernel(const int* __restrict__ src,
                                                   const int* __restrict__ dst) {
    int t    = blockIdx.x * blockDim.x + threadIdx.x;
    int edge = t >> 4;
    int lane = t & 15;
    if (edge >= N_EDGES) return;

    int s = src[edge];          // broadcast within half-warp
    int d = dst[edge];

    const uint4* fh = (const uint4*)g_fh;                 // row = 256 B = 16 x uint4
    uint4 a = fh[s * 16 + lane];
    uint4 b = fh[d * 16 + lane];

    const __half2* ah = (const __half2*)&a;
    const __half2* bh = (const __half2*)&b;
    float acc = 0.0f;
#pragma unroll
    for (int j = 0; j < 4; j++) {
        __half2 da = __habs2(__hsub2(ah[j], bh[j]));
        float2 f = __half22float2(da);
        acc += f.x + f.y;
    }

    acc += __shfl_xor_sync(0xffffffffu, acc, 8);
    acc += __shfl_xor_sync(0xffffffffu, acc, 4);
    acc += __shfl_xor_sync(0xffffffffu, acc, 2);
    acc += __shfl_xor_sync(0xffffffffu, acc, 1);

    if (lane == 0) {
        float e  = __expf(-0.01f * acc);
        float ee = __expf(e);
        g_ee[edge] = ee;
        // fixed-point (2^32) accumulation: deterministic (integer add associative)
        unsigned long long q = (unsigned long long)(ee * 4294967296.0f);
        atomicAdd(&g_sum[d], q);
    }
}

// ---------------------------------------------------------------------------
// Kernel 3: out[i] = ee[i] / sum[dst[i]]
// ---------------------------------------------------------------------------
__global__ __launch_bounds__(256) void finalize_kernel(const int* __restrict__ dst,
                                                       float* __restrict__ out) {
    int i = blockIdx.x * blockDim.x + threadIdx.x;
    if (i < N_EDGES) {
        float s = (float)g_sum[dst[i]] * 0x1p-32f;
        out[i] = __fdividef(g_ee[i], s);
    }
}

// ---------------------------------------------------------------------------
extern "C" void kernel_launch(void* const* d_in, const int* in_sizes, int n_in,
                              void* d_out, int out_size) {
    const float4* feats4 = (const float4*)d_in[0];
    const int*    src    = (const int*)d_in[1];
    const int*    dst    = (const int*)d_in[2];
    float*        out    = (float*)d_out;

    convert_kernel<<<(N_NODES * D_FEAT / 4 + 255) / 256, 256>>>(feats4);

    // 16 lanes per edge: 640000 * 16 threads, 256/block
    edge_kernel<<<(N_EDGES * 16) / 256, 256>>>(src, dst);

    finalize_kernel<<<(N_EDGES + 255) / 256, 256>>>(dst, out);
}